// round 12
// baseline (speedup 1.0000x reference)
#include <cuda_runtime.h>
#include <math.h>
#include <stdint.h>

#define NATOM 32768
#define KNBR 16
#define NEDGE (NATOM*KNBR)

__device__ __align__(16) float g_basisT[(size_t)10*NEDGE];   // [b][e]
__device__ __align__(16) float g_Y[(size_t)NEDGE*16];
__device__ __align__(16) float g_featA[(size_t)NATOM*64];
__device__ __align__(16) float g_featB[(size_t)NATOM*64];
__device__ float g_part[64*64];

__device__ __forceinline__ float tf32r(float x) {
    uint32_t u; asm("cvt.rna.tf32.f32 %0, %1;" : "=r"(u) : "f"(x));
    return __uint_as_float(u);
}
__device__ __forceinline__ void mma8(float4& d, uint32_t a0, uint32_t a1,
                                     uint32_t a2, uint32_t a3,
                                     uint32_t b0, uint32_t b1) {
    asm volatile(
        "mma.sync.aligned.m16n8k8.row.col.f32.tf32.tf32.f32 "
        "{%0,%1,%2,%3},{%4,%5,%6,%7},{%8,%9},{%0,%1,%2,%3};"
        : "+f"(d.x), "+f"(d.y), "+f"(d.z), "+f"(d.w)
        : "r"(a0), "r"(a1), "r"(a2), "r"(a3), "r"(b0), "r"(b1));
}
__device__ __forceinline__ float red16(float v) {
    v += __shfl_xor_sync(0xffffffffu, v, 8);
    v += __shfl_xor_sync(0xffffffffu, v, 4);
    v += __shfl_xor_sync(0xffffffffu, v, 2);
    v += __shfl_xor_sync(0xffffffffu, v, 1);
    return v;
}

__global__ void geom_kernel(const float* __restrict__ coords,
                            const float* __restrict__ shift,
                            const int*   __restrict__ nbr)
{
    int e = blockIdx.x*blockDim.x + threadIdx.x;
    if (e >= NEDGE) return;
    int n  = e >> 4;
    int nb = nbr[e];
    float x = coords[3*nb+0] + shift[3*(size_t)e+0] - coords[3*n+0];
    float y = coords[3*nb+1] + shift[3*(size_t)e+1] - coords[3*n+1];
    float z = coords[3*nb+2] + shift[3*(size_t)e+2] - coords[3*n+2];
    float r  = sqrtf(x*x + y*y + z*z);
    float inv = 1.0f/fmaxf(r, 1e-6f);
    float dx = x*inv, dy = y*inv, dz = z*inv;
    float x2 = dx*dx, y2 = dy*dy, z2 = dz*dz;
    float Y[16];
    Y[0]=0.4886025f*dy; Y[1]=0.4886025f*dz; Y[2]=0.4886025f*dx;
    Y[3]=1.0925484f*dx*dy; Y[4]=1.0925484f*dy*dz; Y[5]=0.3153916f*(3.f*z2-1.f);
    Y[6]=1.0925484f*dx*dz; Y[7]=0.5462742f*(x2-y2);
    Y[8]=0.5900436f*dy*(3.f*x2-y2); Y[9]=2.8906114f*dx*dy*dz;
    Y[10]=0.4570458f*dy*(5.f*z2-1.f); Y[11]=0.3731763f*dz*(5.f*z2-3.f);
    Y[12]=0.4570458f*dx*(5.f*z2-1.f); Y[13]=1.4453057f*(x2-y2)*dz;
    Y[14]=0.5900436f*dx*(x2-3.f*y2); Y[15]=0.f;
    float* Yp = g_Y + (size_t)e*16;
#pragma unroll
    for (int q=0;q<4;q++)
        *(float4*)(Yp+4*q) = make_float4(Y[4*q],Y[4*q+1],Y[4*q+2],Y[4*q+3]);
    float mask = (r < 2.0f && r > 1e-6f) ? 1.f : 0.f;
    const float step = 2.0f/9.0f, invstep = 4.5f;
#pragma unroll
    for (int b=0;b<10;b++) {
        float xr = (r - (float)b*step)*invstep;
        float v = 0.f;
        if (fabsf(xr) < 1.0f) { float c = cospif(0.5f*xr); v = c*c; }
        g_basisT[(size_t)b*NEDGE + e] = v*mask;
    }
}

#define HS 140
template<int NW> struct RK {
    static constexpr int NP     = (NW + 7) & ~7;          // 32,160,256
    static constexpr int NPP    = NP + 8;                 // 40,168,264
    static constexpr int NTILES = NP/8;                   // 4,20,32
    static constexpr int SPLIT  = (NTILES + 1)/2;
    static constexpr int NTW    = SPLIT;
    static constexpr int WBF    = (104*NPP > 10816) ? 104*NPP : 10816;
    static constexpr int OFF_H1 = 1000 + WBF;
    static constexpr int OFF_H2 = OFF_H1 + 104*HS;
    static constexpr int SMEMB  = (OFF_H2 + 104*HS)*4;
};

// CONV: 0 = layer0 (const features), 1 = conv12 (full TP), 3 = scalar-only
template<int NW, int CONV>
__global__ void __launch_bounds__(512) fused_kernel(
    const float* __restrict__ W1, const float* __restrict__ W2,
    const float* __restrict__ W3, const int* __restrict__ nbr, int dir)
{
    extern __shared__ float smx[];
    float* s_w1 = smx;                      // [10][100]
    float* s_wB = smx + 1000;               // W2 [104][104] then W3 [104][NPP]
    float* s_h1 = smx + RK<NW>::OFF_H1;     // [k][e] 104xHS
    float* s_h2 = smx + RK<NW>::OFF_H2;     // [j][e] 104xHS (head reused for basis)
    float* s_bT = s_h2;
    float* s_w  = smx;                      // overlay AFTER phase C: [j][132]
    const int tid  = threadIdx.x;
    const int warp = tid >> 5, lane = tid & 31;
    const int g = lane >> 2, t = lane & 3;
    const size_t ebase = (size_t)blockIdx.x*128;

    const float* fin = dir ? g_featB : g_featA;
    float* fout      = dir ? g_featA : g_featB;

    for (int i = tid; i < 1000; i += 512) s_w1[i] = W1[i];
    for (int i = tid; i < 1280; i += 512) {
        int b = i >> 7, e = i & 127;
        s_bT[b*128 + e] = g_basisT[(size_t)b*NEDGE + ebase + e];
    }
    // stage W2 [104][104] division-free
    for (int k = warp; k < 104; k += 16)
        for (int j = lane; j < 104; j += 32)
            s_wB[k*104 + j] = (k < 100 && j < 100) ? tf32r(W2[k*100 + j]) : 0.f;
    for (int i = tid; i < 4*HS; i += 512) s_h1[100*HS + i] = 0.f;
    __syncthreads();

    // phase A: h1[k][e] = tf32(relu(basis @ W1)); 10 k per thread
    if (tid < 320) {
        const int kg = tid >> 5, c0 = (tid & 31)*4;
        float4 bv[10];
#pragma unroll
        for (int b=0;b<10;b++) bv[b] = *(const float4*)&s_bT[b*128 + c0];
#pragma unroll
        for (int kk=0;kk<10;kk++) {
            const int k = kg*10 + kk;
            float ax=0.f, ay=0.f, az=0.f, aw=0.f;
#pragma unroll
            for (int b=0;b<10;b++) {
                float w = s_w1[b*100 + k];
                ax += bv[b].x*w; ay += bv[b].y*w;
                az += bv[b].z*w; aw += bv[b].w*w;
            }
            *(float4*)&s_h1[k*HS + c0] =
                make_float4(tf32r(fmaxf(ax,0.f)), tf32r(fmaxf(ay,0.f)),
                            tf32r(fmaxf(az,0.f)), tf32r(fmaxf(aw,0.f)));
        }
    }
    __syncthreads();

    // phase B (mma): h2 = tf32(relu(h1^T @ W2)); 13 n-tiles, split 7/6 by half
    {
        const int m = warp & 7, half = warp >> 3;
        const int nbeg = half ? 7 : 0, ncnt = half ? 6 : 7;
        const int arow = m*16 + g;
        float4 acc[7];
#pragma unroll
        for (int nt=0;nt<7;nt++) acc[nt] = make_float4(0.f,0.f,0.f,0.f);
        for (int ks = 0; ks < 13; ks++) {
            const int kb = ks*8;
            uint32_t a0 = __float_as_uint(s_h1[(kb+t  )*HS + arow]);
            uint32_t a1 = __float_as_uint(s_h1[(kb+t  )*HS + arow + 8]);
            uint32_t a2 = __float_as_uint(s_h1[(kb+t+4)*HS + arow]);
            uint32_t a3 = __float_as_uint(s_h1[(kb+t+4)*HS + arow + 8]);
#pragma unroll
            for (int nt=0;nt<7;nt++) {
                if (nt < ncnt) {
                    int nb = (nbeg+nt)*8;
                    uint32_t b0 = __float_as_uint(s_wB[(kb+t  )*104 + nb + g]);
                    uint32_t b1 = __float_as_uint(s_wB[(kb+t+4)*104 + nb + g]);
                    mma8(acc[nt], a0,a1,a2,a3, b0,b1);
                }
            }
        }
#pragma unroll
        for (int nt=0;nt<7;nt++)
            if (nt < ncnt) {
                int col = (nbeg+nt)*8 + 2*t;
                int row = m*16 + g;
                s_h2[ col   *HS + row    ] = tf32r(fmaxf(acc[nt].x,0.f));
                s_h2[(col+1)*HS + row    ] = tf32r(fmaxf(acc[nt].y,0.f));
                s_h2[ col   *HS + row + 8] = tf32r(fmaxf(acc[nt].z,0.f));
                s_h2[(col+1)*HS + row + 8] = tf32r(fmaxf(acc[nt].w,0.f));
            }
    }
    __syncthreads();
    // stage W3 [104][NPP] division-free (overwrites W2)
    for (int k = warp; k < 104; k += 16)
        for (int j = lane; j < RK<NW>::NPP; j += 32)
            s_wB[k*RK<NW>::NPP + j] = (k < 100 && j < NW) ? tf32r(W3[k*NW + j]) : 0.f;
    __syncthreads();

    // phase C (mma): w[j][e] = h2^T @ W3, kept in registers
    {
        constexpr int NPP = RK<NW>::NPP;
        constexpr int NTILES = RK<NW>::NTILES;
        constexpr int SPLIT = RK<NW>::SPLIT;
        constexpr int NTW = RK<NW>::NTW;
        const int m = warp & 7, half = warp >> 3;
        const int nbeg = half ? SPLIT : 0;
        const int ncnt = half ? (NTILES - SPLIT) : SPLIT;
        const int arow = m*16 + g;
        float4 acc[NTW];
#pragma unroll
        for (int nt=0;nt<NTW;nt++) acc[nt] = make_float4(0.f,0.f,0.f,0.f);
        for (int ks = 0; ks < 13; ks++) {
            const int kb = ks*8;
            uint32_t a0 = __float_as_uint(s_h2[(kb+t  )*HS + arow]);
            uint32_t a1 = __float_as_uint(s_h2[(kb+t  )*HS + arow + 8]);
            uint32_t a2 = __float_as_uint(s_h2[(kb+t+4)*HS + arow]);
            uint32_t a3 = __float_as_uint(s_h2[(kb+t+4)*HS + arow + 8]);
#pragma unroll
            for (int nt=0;nt<NTW;nt++) {
                if (nt < ncnt) {
                    int nb = (nbeg+nt)*8;
                    uint32_t b0 = __float_as_uint(s_wB[(kb+t  )*NPP + nb + g]);
                    uint32_t b1 = __float_as_uint(s_wB[(kb+t+4)*NPP + nb + g]);
                    mma8(acc[nt], a0,a1,a2,a3, b0,b1);
                }
            }
        }
        __syncthreads();   // all warps done reading s_wB/s_h2 -> safe to overlay
#pragma unroll
        for (int nt=0;nt<NTW;nt++)
            if (nt < ncnt) {
                int j0 = (nbeg+nt)*8 + 2*t;
                int e  = m*16 + g;
                s_w[ j0   *132 + e    ] = acc[nt].x;
                s_w[(j0+1)*132 + e    ] = acc[nt].y;
                s_w[ j0   *132 + e + 8] = acc[nt].z;
                s_w[(j0+1)*132 + e + 8] = acc[nt].w;
            }
    }
    __syncthreads();

    // ---- fused conv epilogue: 4 groups x 128 threads, outputs split by group
    {
        const int wg   = tid >> 7;          // output group 0..3
        const int wtid = tid & 127;         // edge within tile
        const int sub  = wtid & 15;
        const size_t eg = ebase + wtid;
        const int ag = (int)(eg >> 4);
#define SW(j) s_w[(j)*132 + wtid]
        if (CONV == 3) {
            const int nb = nbr[eg];
            const float* fj = fin + (size_t)nb*64;
            float f0[4];
#pragma unroll
            for (int i=0;i<4;i++) f0[i] = 0.5f*fj[i];
            const int obeg = wg*16;
#pragma unroll
            for (int oo=0;oo<16;oo++) {
                int o = obeg + oo;
                float v = SW(o*4)*f0[0] + SW(o*4+1)*f0[1] +
                          SW(o*4+2)*f0[2] + SW(o*4+3)*f0[3];
                v = red16(v);
                if (sub == 0) fout[(size_t)ag*64 + o] = fmaxf(v, 0.f);
            }
        } else {
            const int ML[3] = {3,5,7};
            const int YO[3] = {0,3,8};
            const int FO[3] = {4,16,36};
            float* fo = fout + (size_t)ag*64;
            float f0[4];
            const float* fj = 0;
            if (CONV == 1) {
                const int nb = nbr[eg];
                fj = fin + (size_t)nb*64;
#pragma unroll
                for (int i=0;i<4;i++) f0[i] = 0.5f*fj[i];
            }
            if (wg == 0) {
                // scalar outputs 0..3 (relu)
#pragma unroll
                for (int o=0;o<4;o++) {
                    float v = (CONV == 0) ? SW(o)*0.5f
                        : SW(o*4)*f0[0] + SW(o*4+1)*f0[1] +
                          SW(o*4+2)*f0[2] + SW(o*4+3)*f0[3];
                    v = red16(v);
                    if (sub == 0) fo[o] = fmaxf(v, 0.f);
                }
            } else {
                const int l = wg - 1;
                // gates for this l: sigmoid(out0[4 + l*4 + o])
                float gg[4];
#pragma unroll
                for (int o=0;o<4;o++) {
                    int oi = 4 + l*4 + o;
                    float v = (CONV == 0) ? SW(oi)*0.5f
                        : SW(oi*4)*f0[0] + SW(oi*4+1)*f0[1] +
                          SW(oi*4+2)*f0[2] + SW(oi*4+3)*f0[3];
                    v = red16(v);
                    gg[o] = 1.f/(1.f + expf(-v));
                }
                const float* Yp = g_Y + eg*16;
                float Y[7];
#pragma unroll
                for (int m2=0;m2<7;m2++)
                    if (m2 < ML[l]) Y[m2] = Yp[YO[l]+m2];
                if (CONV == 0) {
#pragma unroll
                    for (int o=0;o<4;o++) {
                        float s = SW(16 + l*4 + o)*0.5f;
#pragma unroll
                        for (int m2=0;m2<7;m2++)
                            if (m2 < ML[l]) {
                                float v = red16(s*Y[m2]);
                                if (sub == 0)
                                    fo[FO[l] + o*ML[l] + m2] = v*gg[o];
                            }
                    }
                } else {
                    float fl[28];
#pragma unroll
                    for (int q=0;q<28;q++)
                        if (q < 4*ML[l]) fl[q] = 0.5f*fj[FO[l]+q];
#pragma unroll
                    for (int o=0;o<4;o++) {
                        int wb = 64 + l*32 + o*4;
                        float s = SW(wb)*f0[0]+SW(wb+1)*f0[1]+
                                  SW(wb+2)*f0[2]+SW(wb+3)*f0[3];
                        float wA[4];
#pragma unroll
                        for (int i=0;i<4;i++) wA[i] = SW(wb+16+i);
#pragma unroll
                        for (int m2=0;m2<7;m2++)
                            if (m2 < ML[l]) {
                                float v = s*Y[m2];
#pragma unroll
                                for (int i=0;i<4;i++) v += wA[i]*fl[i*ML[l]+m2];
                                v = red16(v);
                                if (sub == 0)
                                    fo[FO[l] + o*ML[l] + m2] = v*gg[o];
                            }
                    }
                }
            }
        }
#undef SW
    }
}

__global__ void pool1_kernel()
{
    __shared__ float sm[256];
    int b = blockIdx.x, tid = threadIdx.x, t = tid >> 6, f = tid & 63;
    float s = 0.f;
    for (int a = b*512 + t; a < (b+1)*512; a += 4)
        s += g_featB[(size_t)a*64 + f];
    sm[tid] = s;
    __syncthreads();
    if (t == 0) g_part[b*64+f] = sm[f] + sm[64+f] + sm[128+f] + sm[192+f];
}
__global__ void pool2_kernel(const float* __restrict__ lw,
                             const float* __restrict__ lb, float* out)
{
    __shared__ float pooled[64];
    int tid = threadIdx.x;
    if (tid < 64) {
        float s = 0.f;
        for (int b=0;b<64;b++) s += g_part[b*64+tid];
        pooled[tid] = s*(1.f/32768.f);
    }
    __syncthreads();
    if (tid < 10) {
        float s = lb[tid];
        for (int f=0;f<64;f++) s += pooled[f]*lw[f*10+tid];
        out[tid] = s;
    }
}

extern "C" void kernel_launch(void* const* d_in, const int* in_sizes, int n_in,
                              void* d_out, int out_size)
{
    const float *coords=0,*shift=0,*lw=0,*lb=0;
    const float *w1[4]={0,0,0,0}, *w2[4]={0,0,0,0}, *w3[4]={0,0,0,0};
    const int* nbr=0;
    int n1=0, n2=0, n3m=0;
    for (int i=0;i<n_in;i++) {
        switch (in_sizes[i]) {
            case 98304:   coords = (const float*)d_in[i]; break;
            case 1572864: shift  = (const float*)d_in[i]; break;
            case 524288:  nbr    = (const int*)d_in[i];   break;
            case 1000:    if (n1<4) w1[n1++] = (const float*)d_in[i]; break;
            case 10000:   if (n2<4) w2[n2++] = (const float*)d_in[i]; break;
            case 2800:    w3[0] = (const float*)d_in[i];  break;
            case 16000:   if (n3m<2) w3[1+n3m++] = (const float*)d_in[i]; break;
            case 25600:   w3[3] = (const float*)d_in[i];  break;
            case 640:     lw = (const float*)d_in[i];     break;
            case 10:      lb = (const float*)d_in[i];     break;
            default: break;
        }
    }
    if (!coords || !shift || !nbr || !lw || !lb ||
        !w1[0]||!w1[1]||!w1[2]||!w1[3] || !w2[0]||!w2[1]||!w2[2]||!w2[3] ||
        !w3[0]||!w3[1]||!w3[2]||!w3[3]) {
        pool2_kernel<<<1, 128>>>(lw ? lw : (const float*)d_in[0],
                                 lb ? lb : (const float*)d_in[0], (float*)d_out);
        return;
    }
    float* out = (float*)d_out;

    cudaFuncSetAttribute((const void*)fused_kernel<28,0>,
        cudaFuncAttributeMaxDynamicSharedMemorySize, RK<28>::SMEMB);
    cudaFuncSetAttribute((const void*)fused_kernel<160,1>,
        cudaFuncAttributeMaxDynamicSharedMemorySize, RK<160>::SMEMB);
    cudaFuncSetAttribute((const void*)fused_kernel<256,3>,
        cudaFuncAttributeMaxDynamicSharedMemorySize, RK<256>::SMEMB);

    geom_kernel<<<NEDGE/256, 256>>>(coords, shift, nbr);
    fused_kernel<28,0><<<NEDGE/128, 512, RK<28>::SMEMB>>>(w1[0], w2[0], w3[0], nbr, 1);
    fused_kernel<160,1><<<NEDGE/128, 512, RK<160>::SMEMB>>>(w1[1], w2[1], w3[1], nbr, 0);
    fused_kernel<160,1><<<NEDGE/128, 512, RK<160>::SMEMB>>>(w1[2], w2[2], w3[2], nbr, 1);
    fused_kernel<256,3><<<NEDGE/128, 512, RK<256>::SMEMB>>>(w1[3], w2[3], w3[3], nbr, 0);
    pool1_kernel<<<64, 256>>>();
    pool2_kernel<<<1, 128>>>(lw, lb, out);
}

// round 13
// speedup vs baseline: 1.5235x; 1.5235x over previous
#include <cuda_runtime.h>
#include <math.h>
#include <stdint.h>

#define NATOM 32768
#define KNBR 16
#define NEDGE (NATOM*KNBR)

__device__ __align__(16) float g_basisT[(size_t)10*NEDGE];   // [b][e]
__device__ __align__(16) float g_Y[(size_t)NEDGE*16];
__device__ __align__(16) float g_featA[(size_t)NATOM*64];
__device__ __align__(16) float g_featB[(size_t)NATOM*64];
__device__ float g_part[64*64];

__device__ __forceinline__ float tf32r(float x) {
    uint32_t u; asm("cvt.rna.tf32.f32 %0, %1;" : "=r"(u) : "f"(x));
    return __uint_as_float(u);
}
__device__ __forceinline__ void mma8(float4& d, uint32_t a0, uint32_t a1,
                                     uint32_t a2, uint32_t a3,
                                     uint32_t b0, uint32_t b1) {
    asm volatile(
        "mma.sync.aligned.m16n8k8.row.col.f32.tf32.tf32.f32 "
        "{%0,%1,%2,%3},{%4,%5,%6,%7},{%8,%9},{%0,%1,%2,%3};"
        : "+f"(d.x), "+f"(d.y), "+f"(d.z), "+f"(d.w)
        : "r"(a0), "r"(a1), "r"(a2), "r"(a3), "r"(b0), "r"(b1));
}
__device__ __forceinline__ float red16(float v) {
    v += __shfl_xor_sync(0xffffffffu, v, 8);
    v += __shfl_xor_sync(0xffffffffu, v, 4);
    v += __shfl_xor_sync(0xffffffffu, v, 2);
    v += __shfl_xor_sync(0xffffffffu, v, 1);
    return v;
}

__global__ void geom_kernel(const float* __restrict__ coords,
                            const float* __restrict__ shift,
                            const int*   __restrict__ nbr)
{
    int e = blockIdx.x*blockDim.x + threadIdx.x;
    if (e >= NEDGE) return;
    int n  = e >> 4;
    int nb = nbr[e];
    float x = coords[3*nb+0] + shift[3*(size_t)e+0] - coords[3*n+0];
    float y = coords[3*nb+1] + shift[3*(size_t)e+1] - coords[3*n+1];
    float z = coords[3*nb+2] + shift[3*(size_t)e+2] - coords[3*n+2];
    float r  = sqrtf(x*x + y*y + z*z);
    float inv = 1.0f/fmaxf(r, 1e-6f);
    float dx = x*inv, dy = y*inv, dz = z*inv;
    float x2 = dx*dx, y2 = dy*dy, z2 = dz*dz;
    float Y[16];
    Y[0]=0.4886025f*dy; Y[1]=0.4886025f*dz; Y[2]=0.4886025f*dx;
    Y[3]=1.0925484f*dx*dy; Y[4]=1.0925484f*dy*dz; Y[5]=0.3153916f*(3.f*z2-1.f);
    Y[6]=1.0925484f*dx*dz; Y[7]=0.5462742f*(x2-y2);
    Y[8]=0.5900436f*dy*(3.f*x2-y2); Y[9]=2.8906114f*dx*dy*dz;
    Y[10]=0.4570458f*dy*(5.f*z2-1.f); Y[11]=0.3731763f*dz*(5.f*z2-3.f);
    Y[12]=0.4570458f*dx*(5.f*z2-1.f); Y[13]=1.4453057f*(x2-y2)*dz;
    Y[14]=0.5900436f*dx*(x2-3.f*y2); Y[15]=0.f;
    float* Yp = g_Y + (size_t)e*16;
#pragma unroll
    for (int q=0;q<4;q++)
        *(float4*)(Yp+4*q) = make_float4(Y[4*q],Y[4*q+1],Y[4*q+2],Y[4*q+3]);
    float mask = (r < 2.0f && r > 1e-6f) ? 1.f : 0.f;
    const float step = 2.0f/9.0f, invstep = 4.5f;
#pragma unroll
    for (int b=0;b<10;b++) {
        float xr = (r - (float)b*step)*invstep;
        float v = 0.f;
        if (fabsf(xr) < 1.0f) { float c = cospif(0.5f*xr); v = c*c; }
        g_basisT[(size_t)b*NEDGE + e] = v*mask;
    }
}

#define HS 140

// ---------------- slim fused kernel (NW=28,160): 2 CTAs/SM -----------------
// smem: s_w1[1000] | s_wB[10816] (W2 104x104, then W3 chunks 104x88) | s_h[104*HS]
// overlay after phase C: s_w[j][132]
template<int NW> struct SK {
    static constexpr int NP     = (NW + 7) & ~7;          // 32,160
    static constexpr int NTILES = NP/8;                   // 4,20
    static constexpr int TPC    = (NW > 80) ? 10 : NTILES; // tiles per chunk
    static constexpr int CHUNKS = NTILES/TPC;             // 2,1
    static constexpr int TH     = TPC/2;                  // per warp-half
    static constexpr int OFF_H  = 1000 + 10816;
    static constexpr int FLOATS = OFF_H + 104*HS;         // 26376
    static constexpr int SMEMB  = FLOATS*4;               // 105504
};

template<int NW, int CONV>  // CONV: 0 = layer0 (const f), 1 = full TP
__global__ void __launch_bounds__(512, 2) fused_slim(
    const float* __restrict__ W1, const float* __restrict__ W2,
    const float* __restrict__ W3, const int* __restrict__ nbr, int dir)
{
    extern __shared__ float smx[];
    float* s_w1 = smx;
    float* s_wB = smx + 1000;
    float* s_h  = smx + SK<NW>::OFF_H;      // h1, then h2 (overwritten)
    float* s_w  = smx;                      // overlay after phase C
    const int tid  = threadIdx.x;
    const int warp = tid >> 5, lane = tid & 31;
    const int g = lane >> 2, t = lane & 3;
    const size_t ebase = (size_t)blockIdx.x*128;
    const float* fin = dir ? g_featB : g_featA;
    float* fout      = dir ? g_featA : g_featB;

    for (int i = tid; i < 1000; i += 512) s_w1[i] = W1[i];
    for (int k = warp; k < 104; k += 16)
        for (int j = lane; j < 104; j += 32)
            s_wB[k*104 + j] = (k < 100 && j < 100) ? tf32r(W2[k*100 + j]) : 0.f;
    for (int i = tid; i < 4*HS; i += 512) s_h[100*HS + i] = 0.f;
    __syncthreads();

    // phase A: h1[k][e] = tf32(relu(basis @ W1)); basis straight from global
    if (tid < 320) {
        const int kg = tid >> 5, c0 = (tid & 31)*4;
        float4 bv[10];
#pragma unroll
        for (int b=0;b<10;b++)
            bv[b] = *(const float4*)&g_basisT[(size_t)b*NEDGE + ebase + c0];
#pragma unroll
        for (int kk=0;kk<10;kk++) {
            const int k = kg*10 + kk;
            float ax=0.f, ay=0.f, az=0.f, aw=0.f;
#pragma unroll
            for (int b=0;b<10;b++) {
                float w = s_w1[b*100 + k];
                ax += bv[b].x*w; ay += bv[b].y*w;
                az += bv[b].z*w; aw += bv[b].w*w;
            }
            *(float4*)&s_h[k*HS + c0] =
                make_float4(tf32r(fmaxf(ax,0.f)), tf32r(fmaxf(ay,0.f)),
                            tf32r(fmaxf(az,0.f)), tf32r(fmaxf(aw,0.f)));
        }
    }
    __syncthreads();

    // phase B: h2 = tf32(relu(h1^T @ W2)); 13 n-tiles split 7/6; write over h1
    {
        const int m = warp & 7, half = warp >> 3;
        const int nbeg = half ? 7 : 0, ncnt = half ? 6 : 7;
        const int arow = m*16 + g;
        float4 acc[7];
#pragma unroll
        for (int nt=0;nt<7;nt++) acc[nt] = make_float4(0.f,0.f,0.f,0.f);
        for (int ks = 0; ks < 13; ks++) {
            const int kb = ks*8;
            uint32_t a0 = __float_as_uint(s_h[(kb+t  )*HS + arow]);
            uint32_t a1 = __float_as_uint(s_h[(kb+t  )*HS + arow + 8]);
            uint32_t a2 = __float_as_uint(s_h[(kb+t+4)*HS + arow]);
            uint32_t a3 = __float_as_uint(s_h[(kb+t+4)*HS + arow + 8]);
#pragma unroll
            for (int nt=0;nt<7;nt++)
                if (nt < ncnt) {
                    int nb = (nbeg+nt)*8;
                    uint32_t b0 = __float_as_uint(s_wB[(kb+t  )*104 + nb + g]);
                    uint32_t b1 = __float_as_uint(s_wB[(kb+t+4)*104 + nb + g]);
                    mma8(acc[nt], a0,a1,a2,a3, b0,b1);
                }
        }
        __syncthreads();   // all h1/W2 reads done -> safe to overwrite h
#pragma unroll
        for (int nt=0;nt<7;nt++)
            if (nt < ncnt) {
                int col = (nbeg+nt)*8 + 2*t;
                int row = m*16 + g;
                s_h[ col   *HS + row    ] = tf32r(fmaxf(acc[nt].x,0.f));
                s_h[(col+1)*HS + row    ] = tf32r(fmaxf(acc[nt].y,0.f));
                s_h[ col   *HS + row + 8] = tf32r(fmaxf(acc[nt].z,0.f));
                s_h[(col+1)*HS + row + 8] = tf32r(fmaxf(acc[nt].w,0.f));
            }
    }

    // phase C: w = h2^T @ W3, W3 staged in 80-col chunks (stride 88)
    {
        constexpr int CHUNKS = SK<NW>::CHUNKS;
        constexpr int TPC = SK<NW>::TPC;
        constexpr int TH  = SK<NW>::TH;
        const int m = warp & 7, half = warp >> 3;
        const int arow = m*16 + g;
        float4 acc[CHUNKS*TH];
#pragma unroll
        for (int i=0;i<CHUNKS*TH;i++) acc[i] = make_float4(0.f,0.f,0.f,0.f);
#pragma unroll
        for (int c = 0; c < CHUNKS; c++) {
            for (int k = warp; k < 104; k += 16)
                for (int j = lane; j < 88; j += 32)
                    s_wB[k*88 + j] = (k < 100 && j < 80 && c*80 + j < NW)
                                       ? tf32r(W3[k*NW + c*80 + j]) : 0.f;
            __syncthreads();
            const int nbeg = half*TH;
            for (int ks = 0; ks < 13; ks++) {
                const int kb = ks*8;
                uint32_t a0 = __float_as_uint(s_h[(kb+t  )*HS + arow]);
                uint32_t a1 = __float_as_uint(s_h[(kb+t  )*HS + arow + 8]);
                uint32_t a2 = __float_as_uint(s_h[(kb+t+4)*HS + arow]);
                uint32_t a3 = __float_as_uint(s_h[(kb+t+4)*HS + arow + 8]);
#pragma unroll
                for (int nt=0;nt<TH;nt++) {
                    int nb = (nbeg+nt)*8;
                    uint32_t b0 = __float_as_uint(s_wB[(kb+t  )*88 + nb + g]);
                    uint32_t b1 = __float_as_uint(s_wB[(kb+t+4)*88 + nb + g]);
                    mma8(acc[c*TH+nt], a0,a1,a2,a3, b0,b1);
                }
            }
            __syncthreads();
        }
        // overlay writes (all s_wB/s_h reads complete)
#pragma unroll
        for (int c=0;c<CHUNKS;c++)
#pragma unroll
            for (int nt=0;nt<TH;nt++) {
                int tile = c*TPC + half*TH + nt;
                int j0 = tile*8 + 2*t;
                int e  = m*16 + g;
                s_w[ j0   *132 + e    ] = acc[c*TH+nt].x;
                s_w[(j0+1)*132 + e    ] = acc[c*TH+nt].y;
                s_w[ j0   *132 + e + 8] = acc[c*TH+nt].z;
                s_w[(j0+1)*132 + e + 8] = acc[c*TH+nt].w;
            }
    }
    __syncthreads();

    // ---- conv epilogue (R11 serial form, 128 threads) ----
    if (tid < 128) {
        const int sub = tid & 15;
        const size_t eg = ebase + tid;
        const int ag = (int)(eg >> 4);
#define SW(j) s_w[(j)*132 + tid]
        const float* Yp = g_Y + eg*16;
        float Y[15];
#pragma unroll
        for (int m2=0;m2<15;m2++) Y[m2] = Yp[m2];
        const int ML[3] = {3,5,7};
        const int YO[3] = {0,3,8};
        const int FO[3] = {4,16,36};
        float* fo = fout + (size_t)ag*64;
        if (CONV == 0) {
            float out0[16];
#pragma unroll
            for (int o=0;o<16;o++) out0[o] = red16(SW(o)*0.5f);
            float gg[12];
#pragma unroll
            for (int j=0;j<12;j++) gg[j] = 1.f/(1.f + expf(-out0[4+j]));
            if (sub == 0)
#pragma unroll
                for (int o=0;o<4;o++) fo[o] = fmaxf(out0[o], 0.f);
#pragma unroll
            for (int l=0;l<3;l++)
#pragma unroll
                for (int o=0;o<4;o++) {
                    float s = SW(16 + l*4 + o)*0.5f;
#pragma unroll
                    for (int m2=0;m2<7;m2++)
                        if (m2 < ML[l]) {
                            float v = red16(s*Y[YO[l]+m2]);
                            if (sub == 0) fo[FO[l] + o*ML[l] + m2] = v*gg[l*4+o];
                        }
                }
        } else {
            const int nb = nbr[eg];
            const float* fj = fin + (size_t)nb*64;
            float f0[4];
#pragma unroll
            for (int i=0;i<4;i++) f0[i] = 0.5f*fj[i];
            float out0[16];
#pragma unroll
            for (int o=0;o<16;o++)
                out0[o] = red16(SW(o*4)*f0[0] + SW(o*4+1)*f0[1] +
                                SW(o*4+2)*f0[2] + SW(o*4+3)*f0[3]);
            float gg[12];
#pragma unroll
            for (int j=0;j<12;j++) gg[j] = 1.f/(1.f + expf(-out0[4+j]));
            if (sub == 0)
#pragma unroll
                for (int o=0;o<4;o++) fo[o] = fmaxf(out0[o], 0.f);
#pragma unroll
            for (int l=0;l<3;l++) {
                float fl[28];
#pragma unroll
                for (int q=0;q<28;q++)
                    if (q < 4*ML[l]) fl[q] = 0.5f*fj[FO[l]+q];
#pragma unroll
                for (int o=0;o<4;o++) {
                    int wb = 64 + l*32 + o*4;
                    float s = SW(wb)*f0[0]+SW(wb+1)*f0[1]+
                              SW(wb+2)*f0[2]+SW(wb+3)*f0[3];
                    float wA[4];
#pragma unroll
                    for (int i=0;i<4;i++) wA[i] = SW(wb+16+i);
#pragma unroll
                    for (int m2=0;m2<7;m2++)
                        if (m2 < ML[l]) {
                            float v = s*Y[YO[l]+m2];
#pragma unroll
                            for (int i=0;i<4;i++) v += wA[i]*fl[i*ML[l]+m2];
                            v = red16(v);
                            if (sub == 0) fo[FO[l] + o*ML[l] + m2] = v*gg[l*4+o];
                        }
                }
            }
        }
#undef SW
    }
}

// ---------------- big fused kernel (NW=256, CONV3) — R11 structure ---------
struct BK {
    static constexpr int NPP    = 264;
    static constexpr int NTILES = 32;
    static constexpr int SPLIT  = 16;
    static constexpr int OFF_H1 = 1000 + 104*264;
    static constexpr int OFF_H2 = OFF_H1 + 104*HS;
    static constexpr int SMEMB  = (OFF_H2 + 104*HS)*4;
};

__global__ void __launch_bounds__(512) fused_big(
    const float* __restrict__ W1, const float* __restrict__ W2,
    const float* __restrict__ W3, const int* __restrict__ nbr, int dir)
{
    constexpr int NW = 256;
    extern __shared__ float smx[];
    float* s_w1 = smx;
    float* s_wB = smx + 1000;
    float* s_h1 = smx + BK::OFF_H1;
    float* s_h2 = smx + BK::OFF_H2;
    float* s_w  = smx;
    const int tid  = threadIdx.x;
    const int warp = tid >> 5, lane = tid & 31;
    const int g = lane >> 2, t = lane & 3;
    const size_t ebase = (size_t)blockIdx.x*128;
    const float* fin = dir ? g_featB : g_featA;
    float* fout      = dir ? g_featA : g_featB;

    for (int i = tid; i < 1000; i += 512) s_w1[i] = W1[i];
    for (int k = warp; k < 104; k += 16)
        for (int j = lane; j < 104; j += 32)
            s_wB[k*104 + j] = (k < 100 && j < 100) ? tf32r(W2[k*100 + j]) : 0.f;
    for (int i = tid; i < 4*HS; i += 512) s_h1[100*HS + i] = 0.f;
    __syncthreads();

    if (tid < 320) {
        const int kg = tid >> 5, c0 = (tid & 31)*4;
        float4 bv[10];
#pragma unroll
        for (int b=0;b<10;b++)
            bv[b] = *(const float4*)&g_basisT[(size_t)b*NEDGE + ebase + c0];
#pragma unroll
        for (int kk=0;kk<10;kk++) {
            const int k = kg*10 + kk;
            float ax=0.f, ay=0.f, az=0.f, aw=0.f;
#pragma unroll
            for (int b=0;b<10;b++) {
                float w = s_w1[b*100 + k];
                ax += bv[b].x*w; ay += bv[b].y*w;
                az += bv[b].z*w; aw += bv[b].w*w;
            }
            *(float4*)&s_h1[k*HS + c0] =
                make_float4(tf32r(fmaxf(ax,0.f)), tf32r(fmaxf(ay,0.f)),
                            tf32r(fmaxf(az,0.f)), tf32r(fmaxf(aw,0.f)));
        }
    }
    __syncthreads();

    {
        const int m = warp & 7, half = warp >> 3;
        const int nbeg = half ? 7 : 0, ncnt = half ? 6 : 7;
        const int arow = m*16 + g;
        float4 acc[7];
#pragma unroll
        for (int nt=0;nt<7;nt++) acc[nt] = make_float4(0.f,0.f,0.f,0.f);
        for (int ks = 0; ks < 13; ks++) {
            const int kb = ks*8;
            uint32_t a0 = __float_as_uint(s_h1[(kb+t  )*HS + arow]);
            uint32_t a1 = __float_as_uint(s_h1[(kb+t  )*HS + arow + 8]);
            uint32_t a2 = __float_as_uint(s_h1[(kb+t+4)*HS + arow]);
            uint32_t a3 = __float_as_uint(s_h1[(kb+t+4)*HS + arow + 8]);
#pragma unroll
            for (int nt=0;nt<7;nt++)
                if (nt < ncnt) {
                    int nb = (nbeg+nt)*8;
                    uint32_t b0 = __float_as_uint(s_wB[(kb+t  )*104 + nb + g]);
                    uint32_t b1 = __float_as_uint(s_wB[(kb+t+4)*104 + nb + g]);
                    mma8(acc[nt], a0,a1,a2,a3, b0,b1);
                }
        }
#pragma unroll
        for (int nt=0;nt<7;nt++)
            if (nt < ncnt) {
                int col = (nbeg+nt)*8 + 2*t;
                int row = m*16 + g;
                s_h2[ col   *HS + row    ] = tf32r(fmaxf(acc[nt].x,0.f));
                s_h2[(col+1)*HS + row    ] = tf32r(fmaxf(acc[nt].y,0.f));
                s_h2[ col   *HS + row + 8] = tf32r(fmaxf(acc[nt].z,0.f));
                s_h2[(col+1)*HS + row + 8] = tf32r(fmaxf(acc[nt].w,0.f));
            }
    }
    __syncthreads();
    for (int k = warp; k < 104; k += 16)
        for (int j = lane; j < BK::NPP; j += 32)
            s_wB[k*BK::NPP + j] = (k < 100 && j < NW) ? tf32r(W3[k*NW + j]) : 0.f;
    __syncthreads();

    {
        const int m = warp & 7, half = warp >> 3;
        const int nbeg = half ? BK::SPLIT : 0;
        const int arow = m*16 + g;
        float4 acc[16];
#pragma unroll
        for (int nt=0;nt<16;nt++) acc[nt] = make_float4(0.f,0.f,0.f,0.f);
        for (int ks = 0; ks < 13; ks++) {
            const int kb = ks*8;
            uint32_t a0 = __float_as_uint(s_h2[(kb+t  )*HS + arow]);
            uint32_t a1 = __float_as_uint(s_h2[(kb+t  )*HS + arow + 8]);
            uint32_t a2 = __float_as_uint(s_h2[(kb+t+4)*HS + arow]);
            uint32_t a3 = __float_as_uint(s_h2[(kb+t+4)*HS + arow + 8]);
#pragma unroll
            for (int nt=0;nt<16;nt++) {
                int nb = (nbeg+nt)*8;
                uint32_t b0 = __float_as_uint(s_wB[(kb+t  )*BK::NPP + nb + g]);
                uint32_t b1 = __float_as_uint(s_wB[(kb+t+4)*BK::NPP + nb + g]);
                mma8(acc[nt], a0,a1,a2,a3, b0,b1);
            }
        }
        __syncthreads();
#pragma unroll
        for (int nt=0;nt<16;nt++) {
            int j0 = (nbeg+nt)*8 + 2*t;
            int e  = m*16 + g;
            s_w[ j0   *132 + e    ] = acc[nt].x;
            s_w[(j0+1)*132 + e    ] = acc[nt].y;
            s_w[ j0   *132 + e + 8] = acc[nt].z;
            s_w[(j0+1)*132 + e + 8] = acc[nt].w;
        }
    }
    __syncthreads();

    if (tid < 128) {
        const int sub = tid & 15;
        const size_t eg = ebase + tid;
        const int ag = (int)(eg >> 4);
#define SW(j) s_w[(j)*132 + tid]
        const int nb = nbr[eg];
        const float* fj = fin + (size_t)nb*64;
        float f0[4];
#pragma unroll
        for (int i=0;i<4;i++) f0[i] = 0.5f*fj[i];
#pragma unroll
        for (int o=0;o<64;o++) {
            float v = SW(o*4)*f0[0] + SW(o*4+1)*f0[1] +
                      SW(o*4+2)*f0[2] + SW(o*4+3)*f0[3];
            v = red16(v);
            if (sub == 0) fout[(size_t)ag*64 + o] = fmaxf(v, 0.f);
        }
#undef SW
    }
}

__global__ void pool1_kernel()
{
    __shared__ float sm[256];
    int b = blockIdx.x, tid = threadIdx.x, t = tid >> 6, f = tid & 63;
    float s = 0.f;
    for (int a = b*512 + t; a < (b+1)*512; a += 4)
        s += g_featB[(size_t)a*64 + f];
    sm[tid] = s;
    __syncthreads();
    if (t == 0) g_part[b*64+f] = sm[f] + sm[64+f] + sm[128+f] + sm[192+f];
}
__global__ void pool2_kernel(const float* __restrict__ lw,
                             const float* __restrict__ lb, float* out)
{
    __shared__ float pooled[64];
    int tid = threadIdx.x;
    if (tid < 64) {
        float s = 0.f;
        for (int b=0;b<64;b++) s += g_part[b*64+tid];
        pooled[tid] = s*(1.f/32768.f);
    }
    __syncthreads();
    if (tid < 10) {
        float s = lb[tid];
        for (int f=0;f<64;f++) s += pooled[f]*lw[f*10+tid];
        out[tid] = s;
    }
}

extern "C" void kernel_launch(void* const* d_in, const int* in_sizes, int n_in,
                              void* d_out, int out_size)
{
    const float *coords=0,*shift=0,*lw=0,*lb=0;
    const float *w1[4]={0,0,0,0}, *w2[4]={0,0,0,0}, *w3[4]={0,0,0,0};
    const int* nbr=0;
    int n1=0, n2=0, n3m=0;
    for (int i=0;i<n_in;i++) {
        switch (in_sizes[i]) {
            case 98304:   coords = (const float*)d_in[i]; break;
            case 1572864: shift  = (const float*)d_in[i]; break;
            case 524288:  nbr    = (const int*)d_in[i];   break;
            case 1000:    if (n1<4) w1[n1++] = (const float*)d_in[i]; break;
            case 10000:   if (n2<4) w2[n2++] = (const float*)d_in[i]; break;
            case 2800:    w3[0] = (const float*)d_in[i];  break;
            case 16000:   if (n3m<2) w3[1+n3m++] = (const float*)d_in[i]; break;
            case 25600:   w3[3] = (const float*)d_in[i];  break;
            case 640:     lw = (const float*)d_in[i];     break;
            case 10:      lb = (const float*)d_in[i];     break;
            default: break;
        }
    }
    if (!coords || !shift || !nbr || !lw || !lb ||
        !w1[0]||!w1[1]||!w1[2]||!w1[3] || !w2[0]||!w2[1]||!w2[2]||!w2[3] ||
        !w3[0]||!w3[1]||!w3[2]||!w3[3]) {
        pool2_kernel<<<1, 128>>>(lw ? lw : (const float*)d_in[0],
                                 lb ? lb : (const float*)d_in[0], (float*)d_out);
        return;
    }
    float* out = (float*)d_out;

    cudaFuncSetAttribute((const void*)fused_slim<28,0>,
        cudaFuncAttributeMaxDynamicSharedMemorySize, SK<28>::SMEMB);
    cudaFuncSetAttribute((const void*)fused_slim<160,1>,
        cudaFuncAttributeMaxDynamicSharedMemorySize, SK<160>::SMEMB);
    cudaFuncSetAttribute((const void*)fused_big,
        cudaFuncAttributeMaxDynamicSharedMemorySize, BK::SMEMB);

    geom_kernel<<<NEDGE/256, 256>>>(coords, shift, nbr);
    fused_slim<28,0><<<NEDGE/128, 512, SK<28>::SMEMB>>>(w1[0], w2[0], w3[0], nbr, 1);
    fused_slim<160,1><<<NEDGE/128, 512, SK<160>::SMEMB>>>(w1[1], w2[1], w3[1], nbr, 0);
    fused_slim<160,1><<<NEDGE/128, 512, SK<160>::SMEMB>>>(w1[2], w2[2], w3[2], nbr, 1);
    fused_big<<<NEDGE/128, 512, BK::SMEMB>>>(w1[3], w2[3], w3[3], nbr, 0);
    pool1_kernel<<<64, 256>>>();
    pool2_kernel<<<1, 128>>>(lw, lb, out);
}

// round 15
// speedup vs baseline: 1.5275x; 1.0026x over previous
#include <cuda_runtime.h>
#include <math.h>
#include <stdint.h>

#define NATOM 32768
#define KNBR 16
#define NEDGE (NATOM*KNBR)

__device__ __align__(16) float g_basisT[(size_t)10*NEDGE];   // [b][e]
__device__ __align__(16) float g_Y[(size_t)NEDGE*16];
__device__ __align__(16) float g_featA[(size_t)NATOM*64];
__device__ __align__(16) float g_featB[(size_t)NATOM*64];
__device__ float g_part[64*64];

__device__ __forceinline__ float tf32r(float x) {
    uint32_t u; asm("cvt.rna.tf32.f32 %0, %1;" : "=r"(u) : "f"(x));
    return __uint_as_float(u);
}
__device__ __forceinline__ void mma8(float4& d, uint32_t a0, uint32_t a1,
                                     uint32_t a2, uint32_t a3,
                                     uint32_t b0, uint32_t b1) {
    asm volatile(
        "mma.sync.aligned.m16n8k8.row.col.f32.tf32.tf32.f32 "
        "{%0,%1,%2,%3},{%4,%5,%6,%7},{%8,%9},{%0,%1,%2,%3};"
        : "+f"(d.x), "+f"(d.y), "+f"(d.z), "+f"(d.w)
        : "r"(a0), "r"(a1), "r"(a2), "r"(a3), "r"(b0), "r"(b1));
}
__device__ __forceinline__ float red16(float v) {
    v += __shfl_xor_sync(0xffffffffu, v, 8);
    v += __shfl_xor_sync(0xffffffffu, v, 4);
    v += __shfl_xor_sync(0xffffffffu, v, 2);
    v += __shfl_xor_sync(0xffffffffu, v, 1);
    return v;
}

__global__ void geom_kernel(const float* __restrict__ coords,
                            const float* __restrict__ shift,
                            const int*   __restrict__ nbr)
{
    int e = blockIdx.x*blockDim.x + threadIdx.x;
    if (e >= NEDGE) return;
    int n  = e >> 4;
    int nb = nbr[e];
    float x = coords[3*nb+0] + shift[3*(size_t)e+0] - coords[3*n+0];
    float y = coords[3*nb+1] + shift[3*(size_t)e+1] - coords[3*n+1];
    float z = coords[3*nb+2] + shift[3*(size_t)e+2] - coords[3*n+2];
    float r  = sqrtf(x*x + y*y + z*z);
    float inv = 1.0f/fmaxf(r, 1e-6f);
    float dx = x*inv, dy = y*inv, dz = z*inv;
    float x2 = dx*dx, y2 = dy*dy, z2 = dz*dz;
    float Y[16];
    Y[0]=0.4886025f*dy; Y[1]=0.4886025f*dz; Y[2]=0.4886025f*dx;
    Y[3]=1.0925484f*dx*dy; Y[4]=1.0925484f*dy*dz; Y[5]=0.3153916f*(3.f*z2-1.f);
    Y[6]=1.0925484f*dx*dz; Y[7]=0.5462742f*(x2-y2);
    Y[8]=0.5900436f*dy*(3.f*x2-y2); Y[9]=2.8906114f*dx*dy*dz;
    Y[10]=0.4570458f*dy*(5.f*z2-1.f); Y[11]=0.3731763f*dz*(5.f*z2-3.f);
    Y[12]=0.4570458f*dx*(5.f*z2-1.f); Y[13]=1.4453057f*(x2-y2)*dz;
    Y[14]=0.5900436f*dx*(x2-3.f*y2); Y[15]=0.f;
    float* Yp = g_Y + (size_t)e*16;
#pragma unroll
    for (int q=0;q<4;q++)
        *(float4*)(Yp+4*q) = make_float4(Y[4*q],Y[4*q+1],Y[4*q+2],Y[4*q+3]);
    float mask = (r < 2.0f && r > 1e-6f) ? 1.f : 0.f;
    const float step = 2.0f/9.0f, invstep = 4.5f;
#pragma unroll
    for (int b=0;b<10;b++) {
        float xr = (r - (float)b*step)*invstep;
        float v = 0.f;
        if (fabsf(xr) < 1.0f) { float c = cospif(0.5f*xr); v = c*c; }
        g_basisT[(size_t)b*NEDGE + e] = v*mask;
    }
}

#define HS 140
#define OFF_H (1000+10816)
#define SLIM_FLOATS (OFF_H + 104*HS)
#define SLIM_SMEMB  (SLIM_FLOATS*4)

template<int NW> struct SK {
    static constexpr int NP     = (NW + 7) & ~7;
    static constexpr int NTILES = NP/8;
    static constexpr int TPC    = (NW > 80) ? 10 : NTILES;
    static constexpr int CHUNKS = NTILES/TPC;
    static constexpr int TH     = TPC/2;
};

template<int NW, int CONV>  // CONV: 0 = layer0 (const f), 1 = full TP
__global__ void __launch_bounds__(512, 2) fused_slim(
    const float* __restrict__ W1, const float* __restrict__ W2,
    const float* __restrict__ W3, const int* __restrict__ nbr, int dir)
{
    extern __shared__ float smx[];
    float* s_w1 = smx;
    float* s_wB = smx + 1000;
    float* s_h  = smx + OFF_H;
    float* s_w  = smx;                      // overlay after phase C
    const int tid  = threadIdx.x;
    const int warp = tid >> 5, lane = tid & 31;
    const int g = lane >> 2, t = lane & 3;
    const size_t ebase = (size_t)blockIdx.x*128;
    const float* fin = dir ? g_featB : g_featA;
    float* fout      = dir ? g_featA : g_featB;

    for (int i = tid; i < 1000; i += 512) s_w1[i] = W1[i];
    for (int k = warp; k < 104; k += 16)
        for (int j = lane; j < 104; j += 32)
            s_wB[k*104 + j] = (k < 100 && j < 100) ? tf32r(W2[k*100 + j]) : 0.f;
    for (int i = tid; i < 4*HS; i += 512) s_h[100*HS + i] = 0.f;
    __syncthreads();

    if (tid < 320) {
        const int kg = tid >> 5, c0 = (tid & 31)*4;
        float4 bv[10];
#pragma unroll
        for (int b=0;b<10;b++)
            bv[b] = *(const float4*)&g_basisT[(size_t)b*NEDGE + ebase + c0];
#pragma unroll
        for (int kk=0;kk<10;kk++) {
            const int k = kg*10 + kk;
            float ax=0.f, ay=0.f, az=0.f, aw=0.f;
#pragma unroll
            for (int b=0;b<10;b++) {
                float w = s_w1[b*100 + k];
                ax += bv[b].x*w; ay += bv[b].y*w;
                az += bv[b].z*w; aw += bv[b].w*w;
            }
            *(float4*)&s_h[k*HS + c0] =
                make_float4(tf32r(fmaxf(ax,0.f)), tf32r(fmaxf(ay,0.f)),
                            tf32r(fmaxf(az,0.f)), tf32r(fmaxf(aw,0.f)));
        }
    }
    __syncthreads();

    // phase B: h2 = tf32(relu(h1^T @ W2)); write over h
    {
        const int m = warp & 7, half = warp >> 3;
        const int nbeg = half ? 7 : 0, ncnt = half ? 6 : 7;
        const int arow = m*16 + g;
        float4 acc[7];
#pragma unroll
        for (int nt=0;nt<7;nt++) acc[nt] = make_float4(0.f,0.f,0.f,0.f);
        for (int ks = 0; ks < 13; ks++) {
            const int kb = ks*8;
            uint32_t a0 = __float_as_uint(s_h[(kb+t  )*HS + arow]);
            uint32_t a1 = __float_as_uint(s_h[(kb+t  )*HS + arow + 8]);
            uint32_t a2 = __float_as_uint(s_h[(kb+t+4)*HS + arow]);
            uint32_t a3 = __float_as_uint(s_h[(kb+t+4)*HS + arow + 8]);
#pragma unroll
            for (int nt=0;nt<7;nt++)
                if (nt < ncnt) {
                    int nb = (nbeg+nt)*8;
                    uint32_t b0 = __float_as_uint(s_wB[(kb+t  )*104 + nb + g]);
                    uint32_t b1 = __float_as_uint(s_wB[(kb+t+4)*104 + nb + g]);
                    mma8(acc[nt], a0,a1,a2,a3, b0,b1);
                }
        }
        __syncthreads();
#pragma unroll
        for (int nt=0;nt<7;nt++)
            if (nt < ncnt) {
                int col = (nbeg+nt)*8 + 2*t;
                int row = m*16 + g;
                s_h[ col   *HS + row    ] = tf32r(fmaxf(acc[nt].x,0.f));
                s_h[(col+1)*HS + row    ] = tf32r(fmaxf(acc[nt].y,0.f));
                s_h[ col   *HS + row + 8] = tf32r(fmaxf(acc[nt].z,0.f));
                s_h[(col+1)*HS + row + 8] = tf32r(fmaxf(acc[nt].w,0.f));
            }
    }

    // phase C: chunks of 80 cols (stride 88)
    {
        constexpr int CHUNKS = SK<NW>::CHUNKS;
        constexpr int TPC = SK<NW>::TPC;
        constexpr int TH  = SK<NW>::TH;
        const int m = warp & 7, half = warp >> 3;
        const int arow = m*16 + g;
        float4 acc[CHUNKS*TH];
#pragma unroll
        for (int i=0;i<CHUNKS*TH;i++) acc[i] = make_float4(0.f,0.f,0.f,0.f);
#pragma unroll
        for (int c = 0; c < CHUNKS; c++) {
            for (int k = warp; k < 104; k += 16)
                for (int j = lane; j < 88; j += 32)
                    s_wB[k*88 + j] = (k < 100 && j < 80 && c*80 + j < NW)
                                       ? tf32r(W3[k*NW + c*80 + j]) : 0.f;
            __syncthreads();
            const int nbeg = half*TH;
            for (int ks = 0; ks < 13; ks++) {
                const int kb = ks*8;
                uint32_t a0 = __float_as_uint(s_h[(kb+t  )*HS + arow]);
                uint32_t a1 = __float_as_uint(s_h[(kb+t  )*HS + arow + 8]);
                uint32_t a2 = __float_as_uint(s_h[(kb+t+4)*HS + arow]);
                uint32_t a3 = __float_as_uint(s_h[(kb+t+4)*HS + arow + 8]);
#pragma unroll
                for (int nt=0;nt<TH;nt++) {
                    int nb = (nbeg+nt)*8;
                    uint32_t b0 = __float_as_uint(s_wB[(kb+t  )*88 + nb + g]);
                    uint32_t b1 = __float_as_uint(s_wB[(kb+t+4)*88 + nb + g]);
                    mma8(acc[c*TH+nt], a0,a1,a2,a3, b0,b1);
                }
            }
            __syncthreads();
        }
#pragma unroll
        for (int c=0;c<CHUNKS;c++)
#pragma unroll
            for (int nt=0;nt<TH;nt++) {
                int tile = c*TPC + half*TH + nt;
                int j0 = tile*8 + 2*t;
                int e  = m*16 + g;
                s_w[ j0   *132 + e    ] = acc[c*TH+nt].x;
                s_w[(j0+1)*132 + e    ] = acc[c*TH+nt].y;
                s_w[ j0   *132 + e + 8] = acc[c*TH+nt].z;
                s_w[(j0+1)*132 + e + 8] = acc[c*TH+nt].w;
            }
    }
    __syncthreads();

    // ---- conv epilogue (serial 128 threads) ----
    if (tid < 128) {
        const int sub = tid & 15;
        const size_t eg = ebase + tid;
        const int ag = (int)(eg >> 4);
#define SW(j) s_w[(j)*132 + tid]
        const float* Yp = g_Y + eg*16;
        float Y[15];
#pragma unroll
        for (int m2=0;m2<15;m2++) Y[m2] = Yp[m2];
        const int ML[3] = {3,5,7};
        const int YO[3] = {0,3,8};
        const int FO[3] = {4,16,36};
        float* fo = fout + (size_t)ag*64;
        if (CONV == 0) {
            float out0[16];
#pragma unroll
            for (int o=0;o<16;o++) out0[o] = red16(SW(o)*0.5f);
            float gg[12];
#pragma unroll
            for (int j=0;j<12;j++) gg[j] = 1.f/(1.f + expf(-out0[4+j]));
            if (sub == 0)
#pragma unroll
                for (int o=0;o<4;o++) fo[o] = fmaxf(out0[o], 0.f);
#pragma unroll
            for (int l=0;l<3;l++)
#pragma unroll
                for (int o=0;o<4;o++) {
                    float s = SW(16 + l*4 + o)*0.5f;
#pragma unroll
                    for (int m2=0;m2<7;m2++)
                        if (m2 < ML[l]) {
                            float v = red16(s*Y[YO[l]+m2]);
                            if (sub == 0) fo[FO[l] + o*ML[l] + m2] = v*gg[l*4+o];
                        }
                }
        } else {
            const int nb = nbr[eg];
            const float* fj = fin + (size_t)nb*64;
            float f0[4];
#pragma unroll
            for (int i=0;i<4;i++) f0[i] = 0.5f*fj[i];
            float out0[16];
#pragma unroll
            for (int o=0;o<16;o++)
                out0[o] = red16(SW(o*4)*f0[0] + SW(o*4+1)*f0[1] +
                                SW(o*4+2)*f0[2] + SW(o*4+3)*f0[3]);
            float gg[12];
#pragma unroll
            for (int j=0;j<12;j++) gg[j] = 1.f/(1.f + expf(-out0[4+j]));
            if (sub == 0)
#pragma unroll
                for (int o=0;o<4;o++) fo[o] = fmaxf(out0[o], 0.f);
#pragma unroll
            for (int l=0;l<3;l++) {
                float fl[28];
#pragma unroll
                for (int q=0;q<28;q++)
                    if (q < 4*ML[l]) fl[q] = 0.5f*fj[FO[l]+q];
#pragma unroll
                for (int o=0;o<4;o++) {
                    int wb = 64 + l*32 + o*4;
                    float s = SW(wb)*f0[0]+SW(wb+1)*f0[1]+
                              SW(wb+2)*f0[2]+SW(wb+3)*f0[3];
                    float wA[4];
#pragma unroll
                    for (int i=0;i<4;i++) wA[i] = SW(wb+16+i);
#pragma unroll
                    for (int m2=0;m2<7;m2++)
                        if (m2 < ML[l]) {
                            float v = s*Y[YO[l]+m2];
#pragma unroll
                            for (int i=0;i<4;i++) v += wA[i]*fl[i*ML[l]+m2];
                            v = red16(v);
                            if (sub == 0) fo[FO[l] + o*ML[l] + m2] = v*gg[l*4+o];
                        }
                }
            }
        }
#undef SW
    }
}

// ---- layer 3 (NW=256, scalar conv): chunked phase C + epilogue, 2 CTAs/SM ----
__global__ void __launch_bounds__(512, 2) fused_slim3(
    const float* __restrict__ W1, const float* __restrict__ W2,
    const float* __restrict__ W3, const int* __restrict__ nbr, int dir)
{
    constexpr int NW = 256;
    extern __shared__ float smx[];
    float* s_w1 = smx;
    float* s_wB = smx + 1000;               // W2 104x104; W3 chunks 104x72; overlay 64x132
    float* s_h  = smx + OFF_H;
    const int tid  = threadIdx.x;
    const int warp = tid >> 5, lane = tid & 31;
    const int g = lane >> 2, t = lane & 3;
    const size_t ebase = (size_t)blockIdx.x*128;
    const float* fin = dir ? g_featB : g_featA;
    float* fout      = dir ? g_featA : g_featB;

    for (int i = tid; i < 1000; i += 512) s_w1[i] = W1[i];
    for (int k = warp; k < 104; k += 16)
        for (int j = lane; j < 104; j += 32)
            s_wB[k*104 + j] = (k < 100 && j < 100) ? tf32r(W2[k*100 + j]) : 0.f;
    for (int i = tid; i < 4*HS; i += 512) s_h[100*HS + i] = 0.f;
    __syncthreads();

    if (tid < 320) {
        const int kg = tid >> 5, c0 = (tid & 31)*4;
        float4 bv[10];
#pragma unroll
        for (int b=0;b<10;b++)
            bv[b] = *(const float4*)&g_basisT[(size_t)b*NEDGE + ebase + c0];
#pragma unroll
        for (int kk=0;kk<10;kk++) {
            const int k = kg*10 + kk;
            float ax=0.f, ay=0.f, az=0.f, aw=0.f;
#pragma unroll
            for (int b=0;b<10;b++) {
                float w = s_w1[b*100 + k];
                ax += bv[b].x*w; ay += bv[b].y*w;
                az += bv[b].z*w; aw += bv[b].w*w;
            }
            *(float4*)&s_h[k*HS + c0] =
                make_float4(tf32r(fmaxf(ax,0.f)), tf32r(fmaxf(ay,0.f)),
                            tf32r(fmaxf(az,0.f)), tf32r(fmaxf(aw,0.f)));
        }
    }
    __syncthreads();

    // phase B, write over h
    {
        const int m = warp & 7, half = warp >> 3;
        const int nbeg = half ? 7 : 0, ncnt = half ? 6 : 7;
        const int arow = m*16 + g;
        float4 acc[7];
#pragma unroll
        for (int nt=0;nt<7;nt++) acc[nt] = make_float4(0.f,0.f,0.f,0.f);
        for (int ks = 0; ks < 13; ks++) {
            const int kb = ks*8;
            uint32_t a0 = __float_as_uint(s_h[(kb+t  )*HS + arow]);
            uint32_t a1 = __float_as_uint(s_h[(kb+t  )*HS + arow + 8]);
            uint32_t a2 = __float_as_uint(s_h[(kb+t+4)*HS + arow]);
            uint32_t a3 = __float_as_uint(s_h[(kb+t+4)*HS + arow + 8]);
#pragma unroll
            for (int nt=0;nt<7;nt++)
                if (nt < ncnt) {
                    int nb = (nbeg+nt)*8;
                    uint32_t b0 = __float_as_uint(s_wB[(kb+t  )*104 + nb + g]);
                    uint32_t b1 = __float_as_uint(s_wB[(kb+t+4)*104 + nb + g]);
                    mma8(acc[nt], a0,a1,a2,a3, b0,b1);
                }
        }
        __syncthreads();
#pragma unroll
        for (int nt=0;nt<7;nt++)
            if (nt < ncnt) {
                int col = (nbeg+nt)*8 + 2*t;
                int row = m*16 + g;
                s_h[ col   *HS + row    ] = tf32r(fmaxf(acc[nt].x,0.f));
                s_h[(col+1)*HS + row    ] = tf32r(fmaxf(acc[nt].y,0.f));
                s_h[ col   *HS + row + 8] = tf32r(fmaxf(acc[nt].z,0.f));
                s_h[(col+1)*HS + row + 8] = tf32r(fmaxf(acc[nt].w,0.f));
            }
    }
    __syncthreads();

    // neighbor features (loaded once; conv3 is scalar-only)
    float f0[4];
    int ag = 0;
    if (tid < 128) {
        const size_t eg = ebase + tid;
        ag = (int)(eg >> 4);
        const int nb = nbr[eg];
        const float* fj = fin + (size_t)nb*64;
#pragma unroll
        for (int i=0;i<4;i++) f0[i] = 0.5f*fj[i];
    }

    // phase C + epilogue in 4 chunks of 64 columns (16 outputs each)
    const int m = warp & 7, half = warp >> 3;
    const int arow = m*16 + g;
#pragma unroll
    for (int c = 0; c < 4; c++) {
        for (int k = warp; k < 104; k += 16)
            for (int j = lane; j < 72; j += 32)
                s_wB[k*72 + j] = (k < 100 && j < 64)
                                   ? tf32r(W3[k*NW + c*64 + j]) : 0.f;
        __syncthreads();
        float4 acc[4];
#pragma unroll
        for (int nt=0;nt<4;nt++) acc[nt] = make_float4(0.f,0.f,0.f,0.f);
        const int nbeg = half*4;
        for (int ks = 0; ks < 13; ks++) {
            const int kb = ks*8;
            uint32_t a0 = __float_as_uint(s_h[(kb+t  )*HS + arow]);
            uint32_t a1 = __float_as_uint(s_h[(kb+t  )*HS + arow + 8]);
            uint32_t a2 = __float_as_uint(s_h[(kb+t+4)*HS + arow]);
            uint32_t a3 = __float_as_uint(s_h[(kb+t+4)*HS + arow + 8]);
#pragma unroll
            for (int nt=0;nt<4;nt++) {
                int nb = (nbeg+nt)*8;
                uint32_t b0 = __float_as_uint(s_wB[(kb+t  )*72 + nb + g]);
                uint32_t b1 = __float_as_uint(s_wB[(kb+t+4)*72 + nb + g]);
                mma8(acc[nt], a0,a1,a2,a3, b0,b1);
            }
        }
        __syncthreads();
#pragma unroll
        for (int nt=0;nt<4;nt++) {
            int jl = (half*4+nt)*8 + 2*t;
            int e  = m*16 + g;
            s_wB[ jl   *132 + e    ] = acc[nt].x;
            s_wB[(jl+1)*132 + e    ] = acc[nt].y;
            s_wB[ jl   *132 + e + 8] = acc[nt].z;
            s_wB[(jl+1)*132 + e + 8] = acc[nt].w;
        }
        __syncthreads();
        if (tid < 128) {
            const int sub = tid & 15;
#pragma unroll
            for (int oo=0;oo<16;oo++) {
                float v = s_wB[(oo*4  )*132 + tid]*f0[0]
                        + s_wB[(oo*4+1)*132 + tid]*f0[1]
                        + s_wB[(oo*4+2)*132 + tid]*f0[2]
                        + s_wB[(oo*4+3)*132 + tid]*f0[3];
                v = red16(v);
                if (sub == 0) fout[(size_t)ag*64 + c*16 + oo] = fmaxf(v, 0.f);
            }
        }
        __syncthreads();
    }
}

__global__ void pool1_kernel()
{
    __shared__ float sm[256];
    int b = blockIdx.x, tid = threadIdx.x, t = tid >> 6, f = tid & 63;
    float s = 0.f;
    for (int a = b*512 + t; a < (b+1)*512; a += 4)
        s += g_featB[(size_t)a*64 + f];
    sm[tid] = s;
    __syncthreads();
    if (t == 0) g_part[b*64+f] = sm[f] + sm[64+f] + sm[128+f] + sm[192+f];
}
__global__ void pool2_kernel(const float* __restrict__ lw,
                             const float* __restrict__ lb, float* out)
{
    __shared__ float pooled[64];
    int tid = threadIdx.x;
    if (tid < 64) {
        float s = 0.f;
        for (int b=0;b<64;b++) s += g_part[b*64+tid];
        pooled[tid] = s*(1.f/32768.f);
    }
    __syncthreads();
    if (tid < 10) {
        float s = lb[tid];
        for (int f=0;f<64;f++) s += pooled[f]*lw[f*10+tid];
        out[tid] = s;
    }
}

extern "C" void kernel_launch(void* const* d_in, const int* in_sizes, int n_in,
                              void* d_out, int out_size)
{
    const float *coords=0,*shift=0,*lw=0,*lb=0;
    const float *w1[4]={0,0,0,0}, *w2[4]={0,0,0,0}, *w3[4]={0,0,0,0};
    const int* nbr=0;
    int n1=0, n2=0, n3m=0;
    for (int i=0;i<n_in;i++) {
        switch (in_sizes[i]) {
            case 98304:   coords = (const float*)d_in[i]; break;
            case 1572864: shift  = (const float*)d_in[i]; break;
            case 524288:  nbr    = (const int*)d_in[i];   break;
            case 1000:    if (n1<4) w1[n1++] = (const float*)d_in[i]; break;
            case 10000:   if (n2<4) w2[n2++] = (const float*)d_in[i]; break;
            case 2800:    w3[0] = (const float*)d_in[i];  break;
            case 16000:   if (n3m<2) w3[1+n3m++] = (const float*)d_in[i]; break;
            case 25600:   w3[3] = (const float*)d_in[i];  break;
            case 640:     lw = (const float*)d_in[i];     break;
            case 10:      lb = (const float*)d_in[i];     break;
            default: break;
        }
    }
    if (!coords || !shift || !nbr || !lw || !lb ||
        !w1[0]||!w1[1]||!w1[2]||!w1[3] || !w2[0]||!w2[1]||!w2[2]||!w2[3] ||
        !w3[0]||!w3[1]||!w3[2]||!w3[3]) {
        pool2_kernel<<<1, 128>>>(lw ? lw : (const float*)d_in[0],
                                 lb ? lb : (const float*)d_in[0], (float*)d_out);
        return;
    }
    float* out = (float*)d_out;

    cudaFuncSetAttribute((const void*)fused_slim<28,0>,
        cudaFuncAttributeMaxDynamicSharedMemorySize, SLIM_SMEMB);
    cudaFuncSetAttribute((const void*)fused_slim<160,1>,
        cudaFuncAttributeMaxDynamicSharedMemorySize, SLIM_SMEMB);
    cudaFuncSetAttribute((const void*)fused_slim3,
        cudaFuncAttributeMaxDynamicSharedMemorySize, SLIM_SMEMB);

    geom_kernel<<<NEDGE/256, 256>>>(coords, shift, nbr);
    fused_slim<28,0><<<NEDGE/128, 512, SLIM_SMEMB>>>(w1[0], w2[0], w3[0], nbr, 1);
    fused_slim<160,1><<<NEDGE/128, 512, SLIM_SMEMB>>>(w1[1], w2[1], w3[1], nbr, 0);
    fused_slim<160,1><<<NEDGE/128, 512, SLIM_SMEMB>>>(w1[2], w2[2], w3[2], nbr, 1);
    fused_slim3<<<NEDGE/128, 512, SLIM_SMEMB>>>(w1[3], w2[3], w3[3], nbr, 0);
    pool1_kernel<<<64, 256>>>();
    pool2_kernel<<<1, 128>>>(lw, lb, out);
}

// round 17
// speedup vs baseline: 1.5963x; 1.0451x over previous
#include <cuda_runtime.h>
#include <math.h>
#include <stdint.h>

#define NATOM 32768
#define KNBR 16
#define NEDGE (NATOM*KNBR)

__device__ __align__(16) float g_basisT[(size_t)10*NEDGE];   // [b][e]
__device__ __align__(16) float g_Y[(size_t)NEDGE*16];
__device__ __align__(16) float g_featA[(size_t)NATOM*64];
__device__ __align__(16) float g_featB[(size_t)NATOM*64];
__device__ float g_part[64*64];

__device__ __forceinline__ float tf32r(float x) {
    uint32_t u; asm("cvt.rna.tf32.f32 %0, %1;" : "=r"(u) : "f"(x));
    return __uint_as_float(u);
}
__device__ __forceinline__ void mma8(float4& d, uint32_t a0, uint32_t a1,
                                     uint32_t a2, uint32_t a3,
                                     uint32_t b0, uint32_t b1) {
    asm volatile(
        "mma.sync.aligned.m16n8k8.row.col.f32.tf32.tf32.f32 "
        "{%0,%1,%2,%3},{%4,%5,%6,%7},{%8,%9},{%0,%1,%2,%3};"
        : "+f"(d.x), "+f"(d.y), "+f"(d.z), "+f"(d.w)
        : "r"(a0), "r"(a1), "r"(a2), "r"(a3), "r"(b0), "r"(b1));
}
__device__ __forceinline__ float red16(float v) {
    v += __shfl_xor_sync(0xffffffffu, v, 8);
    v += __shfl_xor_sync(0xffffffffu, v, 4);
    v += __shfl_xor_sync(0xffffffffu, v, 2);
    v += __shfl_xor_sync(0xffffffffu, v, 1);
    return v;
}

__global__ void geom_kernel(const float* __restrict__ coords,
                            const float* __restrict__ shift,
                            const int*   __restrict__ nbr)
{
    int e = blockIdx.x*blockDim.x + threadIdx.x;
    if (e >= NEDGE) return;
    int n  = e >> 4;
    int nb = nbr[e];
    float x = coords[3*nb+0] + shift[3*(size_t)e+0] - coords[3*n+0];
    float y = coords[3*nb+1] + shift[3*(size_t)e+1] - coords[3*n+1];
    float z = coords[3*nb+2] + shift[3*(size_t)e+2] - coords[3*n+2];
    float r  = sqrtf(x*x + y*y + z*z);
    float inv = 1.0f/fmaxf(r, 1e-6f);
    float dx = x*inv, dy = y*inv, dz = z*inv;
    float x2 = dx*dx, y2 = dy*dy, z2 = dz*dz;
    float Y[16];
    Y[0]=0.4886025f*dy; Y[1]=0.4886025f*dz; Y[2]=0.4886025f*dx;
    Y[3]=1.0925484f*dx*dy; Y[4]=1.0925484f*dy*dz; Y[5]=0.3153916f*(3.f*z2-1.f);
    Y[6]=1.0925484f*dx*dz; Y[7]=0.5462742f*(x2-y2);
    Y[8]=0.5900436f*dy*(3.f*x2-y2); Y[9]=2.8906114f*dx*dy*dz;
    Y[10]=0.4570458f*dy*(5.f*z2-1.f); Y[11]=0.3731763f*dz*(5.f*z2-3.f);
    Y[12]=0.4570458f*dx*(5.f*z2-1.f); Y[13]=1.4453057f*(x2-y2)*dz;
    Y[14]=0.5900436f*dx*(x2-3.f*y2); Y[15]=0.f;
    float* Yp = g_Y + (size_t)e*16;
#pragma unroll
    for (int q=0;q<4;q++)
        *(float4*)(Yp+4*q) = make_float4(Y[4*q],Y[4*q+1],Y[4*q+2],Y[4*q+3]);
    float mask = (r < 2.0f && r > 1e-6f) ? 1.f : 0.f;
    const float step = 2.0f/9.0f, invstep = 4.5f;
#pragma unroll
    for (int b=0;b<10;b++) {
        float xr = (r - (float)b*step)*invstep;
        float v = 0.f;
        if (fabsf(xr) < 1.0f) { float c = cospif(0.5f*xr); v = c*c; }
        g_basisT[(size_t)b*NEDGE + e] = v*mask;
    }
}

#define HS 136
#define OFF_H (1000+10816)
#define SLIM_FLOATS (OFF_H + 104*HS)
#define SLIM_SMEMB  (SLIM_FLOATS*4)

template<int NW> struct SK {
    static constexpr int NP     = (NW + 7) & ~7;
    static constexpr int NTILES = NP/8;
    static constexpr int TPC    = (NW > 80) ? 10 : NTILES;
    static constexpr int CHUNKS = NTILES/TPC;
    static constexpr int TH     = TPC/2;
};

template<int NW, int CONV>  // CONV: 0 = layer0 (const f), 1 = full TP
__global__ void __launch_bounds__(512, 2) fused_slim(
    const float* __restrict__ W1, const float* __restrict__ W2,
    const float* __restrict__ W3, const int* __restrict__ nbr, int dir)
{
    extern __shared__ float smx[];
    float* s_w1 = smx;
    float* s_wB = smx + 1000;
    float* s_h  = smx + OFF_H;
    float* s_w  = smx;                      // overlay after phase C
    const int tid  = threadIdx.x;
    const int warp = tid >> 5, lane = tid & 31;
    const int g = lane >> 2, t = lane & 3;
    const size_t ebase = (size_t)blockIdx.x*128;
    const float* fin = dir ? g_featB : g_featA;
    float* fout      = dir ? g_featA : g_featB;

    for (int i = tid; i < 1000; i += 512) s_w1[i] = W1[i];
    for (int k = warp; k < 104; k += 16)
        for (int j = lane; j < 104; j += 32)
            s_wB[k*104 + j] = (k < 100 && j < 100) ? tf32r(W2[k*100 + j]) : 0.f;
    for (int i = tid; i < 4*HS; i += 512) s_h[100*HS + i] = 0.f;
    __syncthreads();

    if (tid < 320) {
        const int kg = tid >> 5, c0 = (tid & 31)*4;
        float4 bv[10];
#pragma unroll
        for (int b=0;b<10;b++)
            bv[b] = *(const float4*)&g_basisT[(size_t)b*NEDGE + ebase + c0];
#pragma unroll
        for (int kk=0;kk<10;kk++) {
            const int k = kg*10 + kk;
            float ax=0.f, ay=0.f, az=0.f, aw=0.f;
#pragma unroll
            for (int b=0;b<10;b++) {
                float w = s_w1[b*100 + k];
                ax += bv[b].x*w; ay += bv[b].y*w;
                az += bv[b].z*w; aw += bv[b].w*w;
            }
            *(float4*)&s_h[k*HS + c0] =
                make_float4(tf32r(fmaxf(ax,0.f)), tf32r(fmaxf(ay,0.f)),
                            tf32r(fmaxf(az,0.f)), tf32r(fmaxf(aw,0.f)));
        }
    }
    __syncthreads();

    // phase B: h2 = tf32(relu(h1^T @ W2)); write over h
    {
        const int m = warp & 7, half = warp >> 3;
        const int nbeg = half ? 7 : 0, ncnt = half ? 6 : 7;
        const int arow = m*16 + g;
        float4 acc[7];
#pragma unroll
        for (int nt=0;nt<7;nt++) acc[nt] = make_float4(0.f,0.f,0.f,0.f);
        for (int ks = 0; ks < 13; ks++) {
            const int kb = ks*8;
            uint32_t a0 = __float_as_uint(s_h[(kb+t  )*HS + arow]);
            uint32_t a1 = __float_as_uint(s_h[(kb+t  )*HS + arow + 8]);
            uint32_t a2 = __float_as_uint(s_h[(kb+t+4)*HS + arow]);
            uint32_t a3 = __float_as_uint(s_h[(kb+t+4)*HS + arow + 8]);
#pragma unroll
            for (int nt=0;nt<7;nt++)
                if (nt < ncnt) {
                    int nb = (nbeg+nt)*8;
                    uint32_t b0 = __float_as_uint(s_wB[(kb+t  )*104 + nb + g]);
                    uint32_t b1 = __float_as_uint(s_wB[(kb+t+4)*104 + nb + g]);
                    mma8(acc[nt], a0,a1,a2,a3, b0,b1);
                }
        }
        __syncthreads();
#pragma unroll
        for (int nt=0;nt<7;nt++)
            if (nt < ncnt) {
                int col = (nbeg+nt)*8 + 2*t;
                int row = m*16 + g;
                s_h[ col   *HS + row    ] = tf32r(fmaxf(acc[nt].x,0.f));
                s_h[(col+1)*HS + row    ] = tf32r(fmaxf(acc[nt].y,0.f));
                s_h[ col   *HS + row + 8] = tf32r(fmaxf(acc[nt].z,0.f));
                s_h[(col+1)*HS + row + 8] = tf32r(fmaxf(acc[nt].w,0.f));
            }
    }

    // phase C: chunks of 80 cols (stride 88)
    {
        constexpr int CHUNKS = SK<NW>::CHUNKS;
        constexpr int TPC = SK<NW>::TPC;
        constexpr int TH  = SK<NW>::TH;
        const int m = warp & 7, half = warp >> 3;
        const int arow = m*16 + g;
        float4 acc[CHUNKS*TH];
#pragma unroll
        for (int i=0;i<CHUNKS*TH;i++) acc[i] = make_float4(0.f,0.f,0.f,0.f);
#pragma unroll
        for (int c = 0; c < CHUNKS; c++) {
            for (int k = warp; k < 104; k += 16)
                for (int j = lane; j < 88; j += 32)
                    s_wB[k*88 + j] = (k < 100 && j < 80 && c*80 + j < NW)
                                       ? tf32r(W3[k*NW + c*80 + j]) : 0.f;
            __syncthreads();
            const int nbeg = half*TH;
            for (int ks = 0; ks < 13; ks++) {
                const int kb = ks*8;
                uint32_t a0 = __float_as_uint(s_h[(kb+t  )*HS + arow]);
                uint32_t a1 = __float_as_uint(s_h[(kb+t  )*HS + arow + 8]);
                uint32_t a2 = __float_as_uint(s_h[(kb+t+4)*HS + arow]);
                uint32_t a3 = __float_as_uint(s_h[(kb+t+4)*HS + arow + 8]);
#pragma unroll
                for (int nt=0;nt<TH;nt++) {
                    int nb = (nbeg+nt)*8;
                    uint32_t b0 = __float_as_uint(s_wB[(kb+t  )*88 + nb + g]);
                    uint32_t b1 = __float_as_uint(s_wB[(kb+t+4)*88 + nb + g]);
                    mma8(acc[c*TH+nt], a0,a1,a2,a3, b0,b1);
                }
            }
            __syncthreads();
        }
#pragma unroll
        for (int c=0;c<CHUNKS;c++)
#pragma unroll
            for (int nt=0;nt<TH;nt++) {
                int tile = c*TPC + half*TH + nt;
                int j0 = tile*8 + 2*t;
                int e  = m*16 + g;
                s_w[ j0   *132 + e    ] = acc[c*TH+nt].x;
                s_w[(j0+1)*132 + e    ] = acc[c*TH+nt].y;
                s_w[ j0   *132 + e + 8] = acc[c*TH+nt].z;
                s_w[(j0+1)*132 + e + 8] = acc[c*TH+nt].w;
            }
    }
    __syncthreads();

    // ---- conv epilogue (serial 128 threads) ----
    if (tid < 128) {
        const int sub = tid & 15;
        const size_t eg = ebase + tid;
        const int ag = (int)(eg >> 4);
#define SW(j) s_w[(j)*132 + tid]
        const float* Yp = g_Y + eg*16;
        float Y[15];
#pragma unroll
        for (int m2=0;m2<15;m2++) Y[m2] = Yp[m2];
        const int ML[3] = {3,5,7};
        const int YO[3] = {0,3,8};
        const int FO[3] = {4,16,36};
        float* fo = fout + (size_t)ag*64;
        if (CONV == 0) {
            float out0[16];
#pragma unroll
            for (int o=0;o<16;o++) out0[o] = red16(SW(o)*0.5f);
            float gg[12];
#pragma unroll
            for (int j=0;j<12;j++) gg[j] = 1.f/(1.f + expf(-out0[4+j]));
            if (sub == 0)
#pragma unroll
                for (int o=0;o<4;o++) fo[o] = fmaxf(out0[o], 0.f);
#pragma unroll
            for (int l=0;l<3;l++)
#pragma unroll
                for (int o=0;o<4;o++) {
                    float s = SW(16 + l*4 + o)*0.5f;
#pragma unroll
                    for (int m2=0;m2<7;m2++)
                        if (m2 < ML[l]) {
                            float v = red16(s*Y[YO[l]+m2]);
                            if (sub == 0) fo[FO[l] + o*ML[l] + m2] = v*gg[l*4+o];
                        }
                }
        } else {
            const int nb = nbr[eg];
            const float* fj = fin + (size_t)nb*64;
            float f0[4];
#pragma unroll
            for (int i=0;i<4;i++) f0[i] = 0.5f*fj[i];
            float out0[16];
#pragma unroll
            for (int o=0;o<16;o++)
                out0[o] = red16(SW(o*4)*f0[0] + SW(o*4+1)*f0[1] +
                                SW(o*4+2)*f0[2] + SW(o*4+3)*f0[3]);
            float gg[12];
#pragma unroll
            for (int j=0;j<12;j++) gg[j] = 1.f/(1.f + expf(-out0[4+j]));
            if (sub == 0)
#pragma unroll
                for (int o=0;o<4;o++) fo[o] = fmaxf(out0[o], 0.f);
#pragma unroll
            for (int l=0;l<3;l++) {
                float fl[28];
#pragma unroll
                for (int q=0;q<28;q++)
                    if (q < 4*ML[l]) fl[q] = 0.5f*fj[FO[l]+q];
#pragma unroll
                for (int o=0;o<4;o++) {
                    int wb = 64 + l*32 + o*4;
                    float s = SW(wb)*f0[0]+SW(wb+1)*f0[1]+
                              SW(wb+2)*f0[2]+SW(wb+3)*f0[3];
                    float wA[4];
#pragma unroll
                    for (int i=0;i<4;i++) wA[i] = SW(wb+16+i);
#pragma unroll
                    for (int m2=0;m2<7;m2++)
                        if (m2 < ML[l]) {
                            float v = s*Y[YO[l]+m2];
#pragma unroll
                            for (int i=0;i<4;i++) v += wA[i]*fl[i*ML[l]+m2];
                            v = red16(v);
                            if (sub == 0) fo[FO[l] + o*ML[l] + m2] = v*gg[l*4+o];
                        }
                }
            }
        }
#undef SW
    }
}

// ---- layer 3 (NW=256, scalar conv): chunked phase C + epilogue, 2 CTAs/SM ----
__global__ void __launch_bounds__(512, 2) fused_slim3(
    const float* __restrict__ W1, const float* __restrict__ W2,
    const float* __restrict__ W3, const int* __restrict__ nbr, int dir)
{
    constexpr int NW = 256;
    extern __shared__ float smx[];
    float* s_w1 = smx;
    float* s_wB = smx + 1000;               // W2 104x104; W3 chunks 104x72; overlay 64x132
    float* s_h  = smx + OFF_H;
    const int tid  = threadIdx.x;
    const int warp = tid >> 5, lane = tid & 31;
    const int g = lane >> 2, t = lane & 3;
    const size_t ebase = (size_t)blockIdx.x*128;
    const float* fin = dir ? g_featB : g_featA;
    float* fout      = dir ? g_featA : g_featB;

    for (int i = tid; i < 1000; i += 512) s_w1[i] = W1[i];
    for (int k = warp; k < 104; k += 16)
        for (int j = lane; j < 104; j += 32)
            s_wB[k*104 + j] = (k < 100 && j < 100) ? tf32r(W2[k*100 + j]) : 0.f;
    for (int i = tid; i < 4*HS; i += 512) s_h[100*HS + i] = 0.f;
    __syncthreads();

    if (tid < 320) {
        const int kg = tid >> 5, c0 = (tid & 31)*4;
        float4 bv[10];
#pragma unroll
        for (int b=0;b<10;b++)
            bv[b] = *(const float4*)&g_basisT[(size_t)b*NEDGE + ebase + c0];
#pragma unroll
        for (int kk=0;kk<10;kk++) {
            const int k = kg*10 + kk;
            float ax=0.f, ay=0.f, az=0.f, aw=0.f;
#pragma unroll
            for (int b=0;b<10;b++) {
                float w = s_w1[b*100 + k];
                ax += bv[b].x*w; ay += bv[b].y*w;
                az += bv[b].z*w; aw += bv[b].w*w;
            }
            *(float4*)&s_h[k*HS + c0] =
                make_float4(tf32r(fmaxf(ax,0.f)), tf32r(fmaxf(ay,0.f)),
                            tf32r(fmaxf(az,0.f)), tf32r(fmaxf(aw,0.f)));
        }
    }
    __syncthreads();

    // phase B, write over h
    {
        const int m = warp & 7, half = warp >> 3;
        const int nbeg = half ? 7 : 0, ncnt = half ? 6 : 7;
        const int arow = m*16 + g;
        float4 acc[7];
#pragma unroll
        for (int nt=0;nt<7;nt++) acc[nt] = make_float4(0.f,0.f,0.f,0.f);
        for (int ks = 0; ks < 13; ks++) {
            const int kb = ks*8;
            uint32_t a0 = __float_as_uint(s_h[(kb+t  )*HS + arow]);
            uint32_t a1 = __float_as_uint(s_h[(kb+t  )*HS + arow + 8]);
            uint32_t a2 = __float_as_uint(s_h[(kb+t+4)*HS + arow]);
            uint32_t a3 = __float_as_uint(s_h[(kb+t+4)*HS + arow + 8]);
#pragma unroll
            for (int nt=0;nt<7;nt++)
                if (nt < ncnt) {
                    int nb = (nbeg+nt)*8;
                    uint32_t b0 = __float_as_uint(s_wB[(kb+t  )*104 + nb + g]);
                    uint32_t b1 = __float_as_uint(s_wB[(kb+t+4)*104 + nb + g]);
                    mma8(acc[nt], a0,a1,a2,a3, b0,b1);
                }
        }
        __syncthreads();
#pragma unroll
        for (int nt=0;nt<7;nt++)
            if (nt < ncnt) {
                int col = (nbeg+nt)*8 + 2*t;
                int row = m*16 + g;
                s_h[ col   *HS + row    ] = tf32r(fmaxf(acc[nt].x,0.f));
                s_h[(col+1)*HS + row    ] = tf32r(fmaxf(acc[nt].y,0.f));
                s_h[ col   *HS + row + 8] = tf32r(fmaxf(acc[nt].z,0.f));
                s_h[(col+1)*HS + row + 8] = tf32r(fmaxf(acc[nt].w,0.f));
            }
    }
    __syncthreads();

    // neighbor features (loaded once; conv3 is scalar-only)
    float f0[4];
    int ag = 0;
    if (tid < 128) {
        const size_t eg = ebase + tid;
        ag = (int)(eg >> 4);
        const int nb = nbr[eg];
        const float* fj = fin + (size_t)nb*64;
#pragma unroll
        for (int i=0;i<4;i++) f0[i] = 0.5f*fj[i];
    }

    // phase C + epilogue in 4 chunks of 64 columns (16 outputs each)
    const int m = warp & 7, half = warp >> 3;
    const int arow = m*16 + g;
#pragma unroll
    for (int c = 0; c < 4; c++) {
        for (int k = warp; k < 104; k += 16)
            for (int j = lane; j < 72; j += 32)
                s_wB[k*72 + j] = (k < 100 && j < 64)
                                   ? tf32r(W3[k*NW + c*64 + j]) : 0.f;
        __syncthreads();
        float4 acc[4];
#pragma unroll
        for (int nt=0;nt<4;nt++) acc[nt] = make_float4(0.f,0.f,0.f,0.f);
        const int nbeg = half*4;
        for (int ks = 0; ks < 13; ks++) {
            const int kb = ks*8;
            uint32_t a0 = __float_as_uint(s_h[(kb+t  )*HS + arow]);
            uint32_t a1 = __float_as_uint(s_h[(kb+t  )*HS + arow + 8]);
            uint32_t a2 = __float_as_uint(s_h[(kb+t+4)*HS + arow]);
            uint32_t a3 = __float_as_uint(s_h[(kb+t+4)*HS + arow + 8]);
#pragma unroll
            for (int nt=0;nt<4;nt++) {
                int nb = (nbeg+nt)*8;
                uint32_t b0 = __float_as_uint(s_wB[(kb+t  )*72 + nb + g]);
                uint32_t b1 = __float_as_uint(s_wB[(kb+t+4)*72 + nb + g]);
                mma8(acc[nt], a0,a1,a2,a3, b0,b1);
            }
        }
        __syncthreads();
#pragma unroll
        for (int nt=0;nt<4;nt++) {
            int jl = (half*4+nt)*8 + 2*t;
            int e  = m*16 + g;
            s_wB[ jl   *132 + e    ] = acc[nt].x;
            s_wB[(jl+1)*132 + e    ] = acc[nt].y;
            s_wB[ jl   *132 + e + 8] = acc[nt].z;
            s_wB[(jl+1)*132 + e + 8] = acc[nt].w;
        }
        __syncthreads();
        if (tid < 128) {
            const int sub = tid & 15;
#pragma unroll
            for (int oo=0;oo<16;oo++) {
                float v = s_wB[(oo*4  )*132 + tid]*f0[0]
                        + s_wB[(oo*4+1)*132 + tid]*f0[1]
                        + s_wB[(oo*4+2)*132 + tid]*f0[2]
                        + s_wB[(oo*4+3)*132 + tid]*f0[3];
                v = red16(v);
                if (sub == 0) fout[(size_t)ag*64 + c*16 + oo] = fmaxf(v, 0.f);
            }
        }
        __syncthreads();
    }
}

__global__ void pool1_kernel()
{
    __shared__ float sm[256];
    int b = blockIdx.x, tid = threadIdx.x, t = tid >> 6, f = tid & 63;
    float s = 0.f;
    for (int a = b*512 + t; a < (b+1)*512; a += 4)
        s += g_featB[(size_t)a*64 + f];
    sm[tid] = s;
    __syncthreads();
    if (t == 0) g_part[b*64+f] = sm[f] + sm[64+f] + sm[128+f] + sm[192+f];
}
__global__ void pool2_kernel(const float* __restrict__ lw,
                             const float* __restrict__ lb, float* out)
{
    __shared__ float pooled[64];
    int tid = threadIdx.x;
    if (tid < 64) {
        float s = 0.f;
        for (int b=0;b<64;b++) s += g_part[b*64+tid];
        pooled[tid] = s*(1.f/32768.f);
    }
    __syncthreads();
    if (tid < 10) {
        float s = lb[tid];
        for (int f=0;f<64;f++) s += pooled[f]*lw[f*10+tid];
        out[tid] = s;
    }
}

extern "C" void kernel_launch(void* const* d_in, const int* in_sizes, int n_in,
                              void* d_out, int out_size)
{
    const float *coords=0,*shift=0,*lw=0,*lb=0;
    const float *w1[4]={0,0,0,0}, *w2[4]={0,0,0,0}, *w3[4]={0,0,0,0};
    const int* nbr=0;
    int n1=0, n2=0, n3m=0;
    for (int i=0;i<n_in;i++) {
        switch (in_sizes[i]) {
            case 98304:   coords = (const float*)d_in[i]; break;
            case 1572864: shift  = (const float*)d_in[i]; break;
            case 524288:  nbr    = (const int*)d_in[i];   break;
            case 1000:    if (n1<4) w1[n1++] = (const float*)d_in[i]; break;
            case 10000:   if (n2<4) w2[n2++] = (const float*)d_in[i]; break;
            case 2800:    w3[0] = (const float*)d_in[i];  break;
            case 16000:   if (n3m<2) w3[1+n3m++] = (const float*)d_in[i]; break;
            case 25600:   w3[3] = (const float*)d_in[i];  break;
            case 640:     lw = (const float*)d_in[i];     break;
            case 10:      lb = (const float*)d_in[i];     break;
            default: break;
        }
    }
    if (!coords || !shift || !nbr || !lw || !lb ||
        !w1[0]||!w1[1]||!w1[2]||!w1[3] || !w2[0]||!w2[1]||!w2[2]||!w2[3] ||
        !w3[0]||!w3[1]||!w3[2]||!w3[3]) {
        pool2_kernel<<<1, 128>>>(lw ? lw : (const float*)d_in[0],
                                 lb ? lb : (const float*)d_in[0], (float*)d_out);
        return;
    }
    float* out = (float*)d_out;

    cudaFuncSetAttribute((const void*)fused_slim<28,0>,
        cudaFuncAttributeMaxDynamicSharedMemorySize, SLIM_SMEMB);
    cudaFuncSetAttribute((const void*)fused_slim<160,1>,
        cudaFuncAttributeMaxDynamicSharedMemorySize, SLIM_SMEMB);
    cudaFuncSetAttribute((const void*)fused_slim3,
        cudaFuncAttributeMaxDynamicSharedMemorySize, SLIM_SMEMB);

    geom_kernel<<<NEDGE/256, 256>>>(coords, shift, nbr);
    fused_slim<28,0><<<NEDGE/128, 512, SLIM_SMEMB>>>(w1[0], w2[0], w3[0], nbr, 1);
    fused_slim<160,1><<<NEDGE/128, 512, SLIM_SMEMB>>>(w1[1], w2[1], w3[1], nbr, 0);
    fused_slim<160,1><<<NEDGE/128, 512, SLIM_SMEMB>>>(w1[2], w2[2], w3[2], nbr, 1);
    fused_slim3<<<NEDGE/128, 512, SLIM_SMEMB>>>(w1[3], w2[3], w3[3], nbr, 0);
    pool1_kernel<<<64, 256>>>();
    pool2_kernel<<<1, 128>>>(lw, lb, out);
}